// round 5
// baseline (speedup 1.0000x reference)
#include <cuda_runtime.h>
#include <math.h>

#define BB 16
#define TENC 512
#define DENC 512
#define NMEL 80
#define FRAME 240
#define TSTEPS 200
#define NFRAMES 199
#define PRE 256
#define ARNN 1024
#define ADIM 128
#define LK 31
#define GRID 148
#define NTHR 256

// ---------------- device scratch ----------------
__device__ float g_xraw[NFRAMES * BB * FRAME];
__device__ float g_h1[NFRAMES * BB * PRE];
__device__ float g_preT[TSTEPS * PRE * BB];      // [t][f][b]
__device__ float g_pm[BB * TENC * ADIM];         // [b][t][f]
__device__ float g_procloc[BB * TENC * ADIM];    // [b][t][f]
__device__ float g_haT[ARNN * BB];               // [j][b]
__device__ float g_caT[ARNN * BB];
__device__ float g_hdT[ARNN * BB];
__device__ float g_cdT[ARNN * BB];
__device__ float g_ctxT[DENC * BB];
__device__ float g_w[BB * TENC];
__device__ float g_wcum[BB * TENC];
__device__ float g_pA[8 * 4096 * BB];
__device__ float g_pD[16 * 4096 * BB];
__device__ float g_projC[FRAME * BB];
__device__ unsigned g_cnt;
__device__ volatile unsigned g_sense;

__device__ __forceinline__ float sigf(float x) { return 1.f / (1.f + expf(-x)); }
__device__ __forceinline__ float tanh_fast(float x) {
    float y; asm("tanh.approx.f32 %0, %1;" : "=f"(y) : "f"(x)); return y;
}

// ---------------- software grid barrier (load-polling) ----------------
__device__ __forceinline__ void gsync(unsigned ph) {
    __syncthreads();
    if (threadIdx.x == 0) {
        __threadfence();
        if (atomicAdd(&g_cnt, 1u) == GRID - 1) {
            g_cnt = 0;
            __threadfence();
            g_sense = ph;
        } else {
            while (g_sense != ph) __nanosleep(20);
            __threadfence();
        }
    }
    __syncthreads();
}

// ---------------- init ----------------
__global__ void k_init() {
    int i = blockIdx.x * 256 + threadIdx.x;
    if (i == 0) { g_cnt = 0; g_sense = 0; }
    if (i < ARNN * BB) { g_haT[i] = 0.f; g_caT[i] = 0.f; g_hdT[i] = 0.f; g_cdT[i] = 0.f; }
    if (i < DENC * BB) g_ctxT[i] = 0.f;
    if (i < BB * TENC) { g_w[i] = 0.f; g_wcum[i] = 0.f; }
    if (i < PRE * BB) g_preT[i] = 0.f;
}

// ---------------- gather decoder inputs ----------------
__global__ void k_gather(const float* __restrict__ din) {
    int idx = blockIdx.x * 256 + threadIdx.x;
    if (idx >= NFRAMES * BB * FRAME) return;
    int j = idx % FRAME;
    int m = idx / FRAME;
    int b = m % BB;
    int d = m / BB;
    int flat = d * FRAME + j;
    int col = flat % NMEL;
    int row = flat / NMEL;
    g_xraw[idx] = din[(b * NMEL + col) * 600 + row];
}

// ---------------- prologue tiled SGEMM ----------------
__global__ void k_sgemm(const float* __restrict__ A, const float* __restrict__ Bw,
                        float* __restrict__ C, int M, int N, int K, int relu, int mode) {
    __shared__ float As[16][68];
    __shared__ float Bs[16][68];
    int m0 = blockIdx.x * 64, n0 = blockIdx.y * 64;
    int tx = threadIdx.x;
    int tr = tx >> 4, tc = tx & 15;
    float acc[4][4] = {};
    for (int k0 = 0; k0 < K; k0 += 16) {
        for (int i = tx; i < 1024; i += 256) {
            int mm = i >> 4, kk = i & 15;
            int m = m0 + mm, k = k0 + kk;
            As[kk][mm] = (m < M) ? A[(size_t)m * K + k] : 0.f;
            int n = n0 + mm;
            Bs[kk][mm] = (n < N) ? Bw[(size_t)n * K + k] : 0.f;
        }
        __syncthreads();
#pragma unroll
        for (int kk = 0; kk < 16; kk++) {
            float4 a4 = *(const float4*)&As[kk][tr * 4];
            float4 b4 = *(const float4*)&Bs[kk][tc * 4];
            float a_[4] = {a4.x, a4.y, a4.z, a4.w};
            float b_[4] = {b4.x, b4.y, b4.z, b4.w};
#pragma unroll
            for (int r = 0; r < 4; r++)
#pragma unroll
                for (int c = 0; c < 4; c++) acc[r][c] += a_[r] * b_[c];
        }
        __syncthreads();
    }
    for (int r = 0; r < 4; r++)
        for (int c = 0; c < 4; c++) {
            int m = m0 + tr * 4 + r, n = n0 + tc * 4 + c;
            if (m < M && n < N) {
                float v = acc[r][c];
                if (relu) v = fmaxf(v, 0.f);
                if (mode == 0) C[(size_t)m * N + n] = v;
                else {
                    int d = m >> 4, b = m & 15;
                    C[((d + 1) * PRE + n) * BB + b] = v;
                }
            }
        }
}

// ---------------- cooperative stage: global -> smem ----------------
__device__ __forceinline__ void stage(float* dst, const float* src, int nfloats, int tid) {
    const float4* s4 = (const float4*)src;
    float4* d4 = (float4*)dst;
    int n4 = nfloats >> 2;
    for (int i = tid; i < n4; i += NTHR) d4[i] = __ldcg(s4 + i);
}

// ---------------- gate GEMM segment from smem ----------------
__device__ __forceinline__ void gseg_s(const float* __restrict__ wp, int wstr,
                                       const float* __restrict__ sb, int segstart, int kbeg,
                                       int ks, int ke, int row0, int b0, float acc[4][4]) {
#pragma unroll 2
    for (int k = ks; k < ke; k += 4) {
        const float* ab = sb + (k - kbeg) * BB + b0;
        float4 av0 = *(const float4*)(ab);
        float4 av1 = *(const float4*)(ab + 16);
        float4 av2 = *(const float4*)(ab + 32);
        float4 av3 = *(const float4*)(ab + 48);
        int kl = k - segstart;
#pragma unroll
        for (int r = 0; r < 4; r++) {
            float4 wv = *(const float4*)(wp + (size_t)(row0 + r) * wstr + kl);
            acc[r][0] += wv.x * av0.x + wv.y * av1.x + wv.z * av2.x + wv.w * av3.x;
            acc[r][1] += wv.x * av0.y + wv.y * av1.y + wv.z * av2.y + wv.w * av3.y;
            acc[r][2] += wv.x * av0.z + wv.y * av1.z + wv.z * av2.z + wv.w * av3.z;
            acc[r][3] += wv.x * av0.w + wv.y * av1.w + wv.z * av2.w + wv.w * av3.w;
        }
    }
}

// ---------------- staged gate unit: stage window, compute, write partials ----------------
__device__ __forceinline__ void gate_unit_s(
    float* sbuf,
    const float* w0, int s0, const float* a0, int l0,
    const float* w1, int s1, const float* a1, int l1,
    const float* w2, int s2, const float* a2, int l2,
    float* part, int rowbase, int kbeg, int kend, int tid)
{
    int o0s = kbeg > 0 ? kbeg : 0;
    int o0e = kend < l0 ? kend : l0;
    if (o0e > o0s) stage(sbuf + (o0s - kbeg) * BB, a0 + o0s * BB, (o0e - o0s) * BB, tid);
    int s1s = l0, s1e = l0 + l1;
    int o1s = kbeg > s1s ? kbeg : s1s;
    int o1e = kend < s1e ? kend : s1e;
    if (l1 && o1e > o1s) stage(sbuf + (o1s - kbeg) * BB, a1 + (o1s - s1s) * BB, (o1e - o1s) * BB, tid);
    int s2s = s1e, s2e = s1e + l2;
    int o2s = kbeg > s2s ? kbeg : s2s;
    int o2e = kend < s2e ? kend : s2e;
    if (l2 && o2e > o2s) stage(sbuf + (o2s - kbeg) * BB, a2 + (o2s - s2s) * BB, (o2e - o2s) * BB, tid);
    __syncthreads();
    int row0 = rowbase + (tid >> 2) * 4;
    int b0 = (tid & 3) * 4;
    float acc[4][4] = {};
    if (o0e > o0s) gseg_s(w0, s0, sbuf, 0, kbeg, o0s, o0e, row0, b0, acc);
    if (l1 && o1e > o1s) gseg_s(w1, s1, sbuf, s1s, kbeg, o1s, o1e, row0, b0, acc);
    if (l2 && o2e > o2s) gseg_s(w2, s2, sbuf, s2s, kbeg, o2s, o2e, row0, b0, acc);
#pragma unroll
    for (int r = 0; r < 4; r++)
#pragma unroll
        for (int c = 0; c < 4; c++)
            part[(size_t)(row0 + r) * BB + b0 + c] = acc[r][c];
    __syncthreads();
}

// ---------------- LSTM cell element ----------------
__device__ __forceinline__ void cell(const float* part, int nslots,
                                     const float* bih, const float* bhh,
                                     float* hT, float* cT, int i) {
    int b = i & 15, j = i >> 4;
    float g[4];
#pragma unroll
    for (int gi = 0; gi < 4; gi++) {
        int row = gi * 1024 + j;
        float s = bih[row] + bhh[row];
        for (int sl = 0; sl < nslots; sl++)
            s += __ldcg(&part[((size_t)sl * 4096 + row) * BB + b]);
        g[gi] = s;
    }
    float c = sigf(g[1]) * __ldcg(&cT[i]) + sigf(g[0]) * tanhf(g[2]);
    float h = sigf(g[3]) * tanhf(c);
    cT[i] = c;
    hT[i] = h;
}

// ---------------- location conv + dense unit ----------------
__device__ void loc_unit(int b, int tc, const float* __restrict__ lw,
                         const float* __restrict__ ld_, float* sh, int tid) {
    float* win = sh;
    float* locs = sh + 128;
    int t0 = tc * 32;
    if (tid < 128) {
        int ch = tid >> 6, idx = tid & 63;
        int tt = t0 - 15 + idx;
        bool ok = (tt >= 0 && tt < TENC && idx < 62);
        const float* src = ch ? g_wcum : g_w;
        win[ch * 64 + idx] = ok ? __ldcg(&src[b * TENC + tt]) : 0.f;
    }
    __syncthreads();
    for (int i = tid; i < 1024; i += NTHR) {
        int c = i >> 5, tt = i & 31;
        float acc = 0.f;
#pragma unroll
        for (int ch = 0; ch < 2; ch++)
#pragma unroll
            for (int kk = 0; kk < LK; kk++)
                acc += win[ch * 64 + tt + kk] * lw[c * 62 + ch * LK + kk];
        locs[c * 33 + tt] = acc;
    }
    __syncthreads();
    int f = tid & 127, th = tid >> 7;
    float ldr[32];
#pragma unroll
    for (int c = 0; c < 32; c++) ldr[c] = ld_[f * 32 + c];
    for (int tt = th * 16; tt < th * 16 + 16; tt++) {
        float acc = 0.f;
#pragma unroll
        for (int c = 0; c < 32; c++) acc += locs[c * 33 + tt] * ldr[c];
        g_procloc[((size_t)(b * TENC + t0 + tt)) * ADIM + f] = acc;
    }
    __syncthreads();
}

// ---------------- projection h-part (staged), writes output frame t_prev ----------------
__device__ void proj_h_unit(int t_prev, int rbase, const float* __restrict__ proj_w,
                            const float* __restrict__ proj_b, float* __restrict__ out_mel,
                            float* sbuf, int tid) {
    int r = rbase + (tid >> 4), b = tid & 15;
    float acc = 0.f;
    for (int ch = 0; ch < 4; ch++) {
        stage(sbuf, g_hdT + ch * 256 * BB, 256 * BB, tid);
        __syncthreads();
        if (tid < 128) {
            const float* wr = proj_w + (size_t)r * 1536 + ch * 256;
#pragma unroll 4
            for (int k = 0; k < 256; k += 4) {
                float4 wv = *(const float4*)(wr + k);
                acc += wv.x * sbuf[(k + 0) * BB + b] + wv.y * sbuf[(k + 1) * BB + b] +
                       wv.z * sbuf[(k + 2) * BB + b] + wv.w * sbuf[(k + 3) * BB + b];
            }
        }
        __syncthreads();
    }
    if (tid < 128) {
        acc += __ldcg(&g_projC[r * BB + b]) + proj_b[r];
        int flat = t_prev * FRAME + r;
        int u = flat / NMEL, m = flat % NMEL;
        out_mel[(size_t)b * (NMEL * 600) + m * 600 + u] = acc;
    }
}

// ---------------- the persistent megakernel ----------------
__global__ void __launch_bounds__(NTHR) k_mega(
    const float* __restrict__ memory, const int* __restrict__ mlen,
    const float* __restrict__ aw_ih, const float* __restrict__ aw_hh,
    const float* __restrict__ ab_ih, const float* __restrict__ ab_hh,
    const float* __restrict__ dw_ih, const float* __restrict__ dw_hh,
    const float* __restrict__ db_ih, const float* __restrict__ db_hh,
    const float* __restrict__ Wq, const float* __restrict__ v_att,
    const float* __restrict__ lconv, const float* __restrict__ ldense,
    const float* __restrict__ proj_w, const float* __restrict__ proj_b,
    float* __restrict__ out_mel, float* __restrict__ out_align)
{
    __shared__ float sh[1184];
    __shared__ float sbuf[8192];
    int cta = blockIdx.x, tid = threadIdx.x;
    unsigned ph = 0;

    for (int t = 0; t < TSTEPS; t++) {
        // ===== P1: loc + attn-gate partials =====
        if (cta < 128) {
            int rc = cta >> 3, kc = cta & 7;
            // att_w_ih is (4096, 768): input = [prenet(256); ctx(512)]. Stride 768!
            gate_unit_s(sbuf,
                        aw_ih, 768, g_preT + (size_t)t * PRE * BB, 256,
                        aw_ih + 256, 768, g_ctxT, 512,
                        aw_hh, 1024, g_haT, 1024,
                        g_pA + (size_t)kc * 4096 * BB, rc * 256, kc * 224, kc * 224 + 224, tid);
            loc_unit(cta >> 4, cta & 15, lconv, ldense, sh, tid);
        } else {
            for (int u = 128 + (cta - 128); u < 256; u += 20)
                loc_unit(u >> 4, u & 15, lconv, ldense, sh, tid);
        }
        gsync(++ph);

        // ===== P2: attention LSTM cell || projection(t-1) h-part =====
        if (cta < 64) cell(g_pA, 8, ab_ih, ab_hh, g_haT, g_caT, cta * NTHR + tid);
        else if (t > 0 && cta < 94)
            proj_h_unit(t - 1, (cta - 64) * 8, proj_w, proj_b, out_mel, sbuf, tid);
        gsync(++ph);

        // ===== P3: dec-gate h-parts || attention chain =====
        if (cta < 128) {
            int rc = cta >> 3, kc = cta & 7;
            gate_unit_s(sbuf,
                        dw_ih, 1536, g_haT, 1024,
                        dw_hh, 1024, g_hdT, 1024,
                        (const float*)0, 0, (const float*)0, 0,
                        g_pD + (size_t)kc * 4096 * BB, rc * 256, kc * 256, kc * 256 + 256, tid);
        } else if (cta >= 132) {
            int b = cta - 132;
            // stage h_a column b
            for (int k = tid; k < ARNN; k += NTHR) sbuf[k] = __ldcg(&g_haT[k * BB + b]);
            __syncthreads();
            // q = Wq @ h_a[b]
            if (tid < 128) {
                const float* wr = Wq + (size_t)tid * ARNN;
                float acc = 0.f;
#pragma unroll 4
                for (int k = 0; k < ARNN; k += 4) {
                    float4 wv = *(const float4*)(wr + k);
                    acc += wv.x * sbuf[k] + wv.y * sbuf[k + 1] + wv.z * sbuf[k + 2] + wv.w * sbuf[k + 3];
                }
                sh[tid] = acc;               // qs
                sh[128 + tid] = v_att[tid];  // vs
            }
            __syncthreads();
            // energies + mask
            int L = mlen[b];
            float ev[2];
#pragma unroll
            for (int it = 0; it < 2; it++) {
                int tt = tid + it * 256;
                const float* pl = &g_procloc[((size_t)b * TENC + tt) * ADIM];
                const float* pv = &g_pm[((size_t)b * TENC + tt) * ADIM];
                float acc = 0.f;
#pragma unroll 4
                for (int f = 0; f < ADIM; f += 4) {
                    float4 a = __ldcg((const float4*)(pl + f));
                    float4 p = *(const float4*)(pv + f);
                    acc += sh[128 + f + 0] * tanh_fast(sh[f + 0] + a.x + p.x);
                    acc += sh[128 + f + 1] * tanh_fast(sh[f + 1] + a.y + p.y);
                    acc += sh[128 + f + 2] * tanh_fast(sh[f + 2] + a.z + p.z);
                    acc += sh[128 + f + 3] * tanh_fast(sh[f + 3] + a.w + p.w);
                }
                ev[it] = (tt >= L) ? -1e9f : acc;
            }
            // softmax over 512
            sh[256 + tid] = fmaxf(ev[0], ev[1]);
            __syncthreads();
            for (int s = 128; s > 0; s >>= 1) {
                if (tid < s) sh[256 + tid] = fmaxf(sh[256 + tid], sh[256 + tid + s]);
                __syncthreads();
            }
            float mx = sh[256];
            __syncthreads();
            float ex0 = expf(ev[0] - mx), ex1 = expf(ev[1] - mx);
            sh[256 + tid] = ex0 + ex1;
            __syncthreads();
            for (int s = 128; s > 0; s >>= 1) {
                if (tid < s) sh[256 + tid] += sh[256 + tid + s];
                __syncthreads();
            }
            float inv = 1.f / sh[256];
            {
                int tt = tid;
                float wv = ex0 * inv;
                g_w[b * TENC + tt] = wv;
                g_wcum[b * TENC + tt] = __ldcg(&g_wcum[b * TENC + tt]) + wv;
                out_align[((size_t)b * TSTEPS + t) * TENC + tt] = wv;
                tt = tid + 256;
                wv = ex1 * inv;
                g_w[b * TENC + tt] = wv;
                g_wcum[b * TENC + tt] = __ldcg(&g_wcum[b * TENC + tt]) + wv;
                out_align[((size_t)b * TSTEPS + t) * TENC + tt] = wv;
            }
        }
        gsync(++ph);

        // ===== P4: context = w @ memory =====
        if (cta < 128) {
            int b = cta >> 3, d0 = (cta & 7) * 64;
            for (int i = tid; i < TENC; i += NTHR) sh[i] = __ldcg(&g_w[b * TENC + i]);
            __syncthreads();
            int dd = tid & 63, tq = tid >> 6;
            const float* mb = memory + ((size_t)b * TENC) * DENC + d0 + dd;
            float acc = 0.f;
#pragma unroll 8
            for (int tt = tq * 128; tt < tq * 128 + 128; tt++)
                acc += sh[tt] * mb[(size_t)tt * DENC];
            sh[512 + tid] = acc;
            __syncthreads();
            if (tid < 64) {
                float s = sh[512 + tid] + sh[576 + tid] + sh[640 + tid] + sh[704 + tid];
                g_ctxT[(d0 + tid) * BB + b] = s;
            }
            __syncthreads();
        }
        gsync(++ph);

        // ===== P5: dec-gate ctx-part + proj ctx-part =====
        if (cta < 128) {
            int rc = cta >> 3, kc = cta & 7;
            gate_unit_s(sbuf,
                        dw_ih + 1024, 1536, g_ctxT, 512,
                        (const float*)0, 0, (const float*)0, 0,
                        (const float*)0, 0, (const float*)0, 0,
                        g_pD + (size_t)(8 + kc) * 4096 * BB, rc * 256, kc * 64, kc * 64 + 64, tid);
        } else {
            stage(sbuf, g_ctxT, DENC * BB, tid);
            __syncthreads();
            if (tid < 192) {
                int r = (cta - 128) * 12 + (tid >> 4), b = tid & 15;
                const float* wr = proj_w + (size_t)r * 1536 + 1024;
                float acc = 0.f;
#pragma unroll 4
                for (int k = 0; k < 512; k += 4) {
                    float4 wv = *(const float4*)(wr + k);
                    acc += wv.x * sbuf[(k + 0) * BB + b] + wv.y * sbuf[(k + 1) * BB + b] +
                           wv.z * sbuf[(k + 2) * BB + b] + wv.w * sbuf[(k + 3) * BB + b];
                }
                g_projC[r * BB + b] = acc;
            }
            __syncthreads();
        }
        gsync(++ph);

        // ===== P6: decoder LSTM cell =====
        if (cta < 64) cell(g_pD, 16, db_ih, db_hh, g_hdT, g_cdT, cta * NTHR + tid);
        gsync(++ph);
    }

    // epilogue: final projection for t = TSTEPS-1
    if (cta >= 64 && cta < 94)
        proj_h_unit(TSTEPS - 1, (cta - 64) * 8, proj_w, proj_b, out_mel, sbuf, tid);
}

// ---------------- launch ----------------
extern "C" void kernel_launch(void* const* d_in, const int* in_sizes, int n_in,
                              void* d_out, int out_size) {
    const float* memory = (const float*)d_in[0];
    const float* dec_in = (const float*)d_in[1];
    const int*   mlen   = (const int*)d_in[2];
    const float* pw1    = (const float*)d_in[3];
    const float* pw2    = (const float*)d_in[4];
    const float* aw_ih  = (const float*)d_in[5];
    const float* aw_hh  = (const float*)d_in[6];
    const float* ab_ih  = (const float*)d_in[7];
    const float* ab_hh  = (const float*)d_in[8];
    const float* dw_ih  = (const float*)d_in[9];
    const float* dw_hh  = (const float*)d_in[10];
    const float* db_ih  = (const float*)d_in[11];
    const float* db_hh  = (const float*)d_in[12];
    const float* Wq     = (const float*)d_in[13];
    const float* Wm     = (const float*)d_in[14];
    const float* v_att  = (const float*)d_in[15];
    const float* lconv  = (const float*)d_in[16];
    const float* ldense = (const float*)d_in[17];
    const float* proj_w = (const float*)d_in[18];
    const float* proj_b = (const float*)d_in[19];

    float* out = (float*)d_out;
    float* align_out = out + (size_t)BB * NMEL * 600;

    float *s_xraw, *s_h1, *s_preT, *s_pm;
    cudaGetSymbolAddress((void**)&s_xraw, g_xraw);
    cudaGetSymbolAddress((void**)&s_h1, g_h1);
    cudaGetSymbolAddress((void**)&s_preT, g_preT);
    cudaGetSymbolAddress((void**)&s_pm, g_pm);

    k_init<<<256, 256>>>();
    k_gather<<<(NFRAMES * BB * FRAME + 255) / 256, 256>>>(dec_in);
    k_sgemm<<<dim3(50, 4), 256>>>(s_xraw, pw1, s_h1, NFRAMES * BB, PRE, FRAME, 1, 0);
    k_sgemm<<<dim3(50, 4), 256>>>(s_h1, pw2, s_preT, NFRAMES * BB, PRE, PRE, 1, 1);
    k_sgemm<<<dim3(128, 2), 256>>>(memory, Wm, s_pm, BB * TENC, ADIM, DENC, 0, 0);

    k_mega<<<GRID, NTHR>>>(memory, mlen,
                           aw_ih, aw_hh, ab_ih, ab_hh,
                           dw_ih, dw_hh, db_ih, db_hh,
                           Wq, v_att, lconv, ldense, proj_w, proj_b,
                           out, align_out);
}